// round 8
// baseline (speedup 1.0000x reference)
#include <cuda_runtime.h>
#include <stdint.h>

#define NB 8
#define NN 4096
#define DD 512

// Supertile = 256x256, CTA = 128x256 (row half), warp tile 64x64 (8 warps 2x4)
#define SPD 16                 // supertiles per dim
#define NST 136                // SPD*(SPD+1)/2
#define BK 16
#define NKT (DD / BK)          // 32
#define THREADS 256

// stage: A 128 rows x 80B = 10240, B 256 rows x 80B = 20480
#define STAGE_BYTES 30720
#define SQROW_OFF  122880
#define INVROW_OFF 123392
#define SQCOL_OFF  123904
#define INVCOL_OFF 124928
#define SMEM_TOTAL 125952

__device__ float g_sq[NB * NN];

static __device__ __forceinline__ uint32_t smem_u32(const void* p) {
    uint32_t a;
    asm("{ .reg .u64 t; cvta.to.shared.u64 t, %1; cvt.u32.u64 %0, t; }" : "=r"(a) : "l"(p));
    return a;
}

#define CP16(dst, src) \
    asm volatile("cp.async.cg.shared.global [%0], [%1], 16;" :: "r"(dst), "l"(src))
#define CP_COMMIT() asm volatile("cp.async.commit_group;" ::: "memory")
#define CP_WAIT(n)  asm volatile("cp.async.wait_group %0;" :: "n"(n) : "memory")

static __device__ __forceinline__ void ldsm4(uint32_t r[4], uint32_t addr) {
    asm volatile("ldmatrix.sync.aligned.m8n8.x4.shared.b16 {%0,%1,%2,%3}, [%4];"
                 : "=r"(r[0]), "=r"(r[1]), "=r"(r[2]), "=r"(r[3]) : "r"(addr));
}

static __device__ __forceinline__ void mma_tf32(float c[4], const uint32_t a[4],
                                                const uint32_t b0, const uint32_t b1) {
    asm volatile(
        "mma.sync.aligned.m16n8k8.row.col.f32.tf32.tf32.f32 "
        "{%0,%1,%2,%3}, {%4,%5,%6,%7}, {%8,%9}, {%0,%1,%2,%3};\n"
        : "+f"(c[0]), "+f"(c[1]), "+f"(c[2]), "+f"(c[3])
        : "r"(a[0]), "r"(a[1]), "r"(a[2]), "r"(a[3]), "r"(b0), "r"(b1));
}

static __device__ __forceinline__ float fsqrt_ap(float x) {
    float y; asm("sqrt.approx.f32 %0, %1;" : "=f"(y) : "f"(x)); return y;
}

// ---------------------------------------------------------------------------
// Kernel 1: per-row squared norms
// ---------------------------------------------------------------------------
__global__ void sq_kernel(const float* __restrict__ x) {
    int row  = blockIdx.x * 8 + (threadIdx.x >> 5);
    int lane = threadIdx.x & 31;
    const float4* p = reinterpret_cast<const float4*>(x + (size_t)row * DD);
    float s = 0.0f;
#pragma unroll
    for (int i = 0; i < 4; ++i) {
        float4 v = p[lane + i * 32];
        s += v.x * v.x + v.y * v.y + v.z * v.z + v.w * v.w;
    }
#pragma unroll
    for (int o = 16; o > 0; o >>= 1) s += __shfl_xor_sync(0xffffffffu, s, o);
    if (lane == 0) g_sq[row] = s;
}

// ---------------------------------------------------------------------------
// Kernel 2: symmetric supertile tf32 Gram + fused hyperbolic epilogue.
// CTA = 128x256 output, 8 warps (2x4), warp tile 64x64, cp.async 4-stage.
// Direct + mirror writes straight from registers.
// ---------------------------------------------------------------------------
__global__ __launch_bounds__(THREADS) void hyp_sym2(const float* __restrict__ X,
                                                    float* __restrict__ out) {
    extern __shared__ __align__(1024) char smem[];
    const uint32_t sbase = smem_u32(smem);
    float* sqRowS  = reinterpret_cast<float*>(smem + SQROW_OFF);
    float* invRowS = reinterpret_cast<float*>(smem + INVROW_OFF);
    float* sqColS  = reinterpret_cast<float*>(smem + SQCOL_OFF);
    float* invColS = reinterpret_cast<float*>(smem + INVCOL_OFF);

    const int b = blockIdx.z;
    // decode supertile (TR, TC), TR <= TC, plus row half h
    int st = blockIdx.x >> 1;
    const int h = blockIdx.x & 1;
    int TR = 0;
    while (st >= SPD - TR) { st -= SPD - TR; ++TR; }
    const int TC = TR + st;
    const int rowBase = TR * 256 + h * 128;
    const int colBase = TC * 256;

    const int tid  = threadIdx.x;
    const int lane = tid & 31;
    const int wid  = tid >> 5;
    const int wr   = (wid & 1) * 64;   // warp row origin (0/64)
    const int wc   = (wid >> 1) * 64;  // warp col origin (0/64/128/192)
    const int gr   = lane >> 2;
    const int gq   = lane & 3;

    const float* Xb = X + (size_t)b * NN * DD;

    // cp.async geometry: 6 x 16B per thread per k-tile
    const int rowT = tid >> 2;          // 0..63
    const int seg  = tid & 3;
    const float* pA0 = Xb + (size_t)(rowBase + rowT) * DD + seg * 4;
    const float* pB0 = Xb + (size_t)(colBase + rowT) * DD + seg * 4;
    const uint32_t dA0 = (uint32_t)rowT * 80 + seg * 16;

#define LOAD_TILE(g, s)                                                        \
    do {                                                                       \
        uint32_t sb = sbase + (uint32_t)(s) * STAGE_BYTES;                     \
        const float* ga = pA0 + (size_t)(g) * BK;                              \
        const float* gb = pB0 + (size_t)(g) * BK;                              \
        CP16(sb + dA0,            ga);                                         \
        CP16(sb + dA0 + 64 * 80,  ga + (size_t)64 * DD);                       \
        CP16(sb + 10240 + dA0,             gb);                                \
        CP16(sb + 10240 + dA0 +  64 * 80,  gb + (size_t)64  * DD);             \
        CP16(sb + 10240 + dA0 + 128 * 80,  gb + (size_t)128 * DD);             \
        CP16(sb + 10240 + dA0 + 192 * 80,  gb + (size_t)192 * DD);             \
    } while (0)

    // ldmatrix per-lane offsets
    uint32_t offA[4], offB[4];
    {
        const int r16  = lane & 15;
        const int s16  = (lane >> 4) * 16;
#pragma unroll
        for (int mi = 0; mi < 4; ++mi)
            offA[mi] = (uint32_t)(wr + mi * 16 + r16) * 80 + s16;
#pragma unroll
        for (int p = 0; p < 4; ++p) {
            int col = wc + (2 * p + (lane >> 4)) * 8 + (lane & 7);
            offB[p] = (uint32_t)col * 80 + ((lane >> 3) & 1) * 16;
        }
    }

    // stage sq / 1/(1-sq)
    {
        float sc = g_sq[b * NN + colBase + tid];
        sqColS[tid] = sc; invColS[tid] = 1.0f / (1.0f - sc);
        if (tid < 128) {
            float sr = g_sq[b * NN + rowBase + tid];
            sqRowS[tid] = sr; invRowS[tid] = 1.0f / (1.0f - sr);
        }
    }

    // prologue: 3 stages
    LOAD_TILE(0, 0); CP_COMMIT();
    LOAD_TILE(1, 1); CP_COMMIT();
    LOAD_TILE(2, 2); CP_COMMIT();

    float c[4][8][4];
#pragma unroll
    for (int mi = 0; mi < 4; ++mi)
#pragma unroll
        for (int ni = 0; ni < 8; ++ni)
#pragma unroll
            for (int v = 0; v < 4; ++v) c[mi][ni][v] = 0.0f;

    for (int kt = 0; kt < NKT; ++kt) {
        CP_WAIT(2);
        __syncthreads();
        if (kt + 3 < NKT) LOAD_TILE(kt + 3, (kt + 3) & 3);
        CP_COMMIT();

        const uint32_t aSt = sbase + (uint32_t)(kt & 3) * STAGE_BYTES;
        const uint32_t bSt = aSt + 10240;
#pragma unroll
        for (int ks = 0; ks < 2; ++ks) {
            uint32_t a[4][4], bb[4][4];
#pragma unroll
            for (int mi = 0; mi < 4; ++mi) ldsm4(a[mi], aSt + offA[mi] + ks * 32);
#pragma unroll
            for (int p = 0; p < 4; ++p)    ldsm4(bb[p], bSt + offB[p] + ks * 32);
#pragma unroll
            for (int mi = 0; mi < 4; ++mi)
#pragma unroll
                for (int p = 0; p < 4; ++p) {
                    mma_tf32(c[mi][2 * p + 0], a[mi], bb[p][0], bb[p][1]);
                    mma_tf32(c[mi][2 * p + 1], a[mi], bb[p][2], bb[p][3]);
                }
        }
    }

    // ---- epilogue: hyperbolic distance, direct + mirror from registers ----
    const bool doMirror = (TR != TC);
#pragma unroll
    for (int mi = 0; mi < 4; ++mi) {
#pragma unroll
        for (int half = 0; half < 2; ++half) {
            const int lr   = wr + mi * 16 + half * 8 + gr;
            const int grow = rowBase + lr;
            const float si  = sqRowS[lr];
            const float tiv = 2.0f * invRowS[lr];
            float* orow = out + ((size_t)b * NN + grow) * NN + colBase;
#pragma unroll
            for (int ni = 0; ni < 8; ++ni) {
                const int lcol = wc + ni * 8 + 2 * gq;
                const float g0 = c[mi][ni][half * 2 + 0];
                const float g1 = c[mi][ni][half * 2 + 1];
                float d20 = fmaxf(si + sqColS[lcol]     - 2.0f * g0, 0.0f);
                float d21 = fmaxf(si + sqColS[lcol + 1] - 2.0f * g1, 0.0f);
                float arg0 = fmaf(fsqrt_ap(d20), tiv * invColS[lcol],     1.0f);
                float arg1 = fmaf(fsqrt_ap(d21), tiv * invColS[lcol + 1], 1.0f);
                float t0 = fmaxf(fmaf(arg0, arg0, -1.0f), 0.0f);
                float t1 = fmaxf(fmaf(arg1, arg1, -1.0f), 0.0f);
                float dist0 = (arg0 > 1.0f) ? __logf(arg0 + fsqrt_ap(t0)) : 0.0f;
                float dist1 = (arg1 > 1.0f) ? __logf(arg1 + fsqrt_ap(t1)) : 0.0f;
                if (grow == colBase + lcol)     dist0 = 0.0f;
                if (grow == colBase + lcol + 1) dist1 = 0.0f;
                *reinterpret_cast<float2*>(orow + lcol) = make_float2(dist0, dist1);
                if (doMirror) {
                    out[((size_t)b * NN + colBase + lcol)     * NN + grow] = dist0;
                    out[((size_t)b * NN + colBase + lcol + 1) * NN + grow] = dist1;
                }
            }
        }
    }
}

extern "C" void kernel_launch(void* const* d_in, const int* in_sizes, int n_in,
                              void* d_out, int out_size) {
    const float* x = (const float*)d_in[0];
    float* out = (float*)d_out;

    cudaFuncSetAttribute(hyp_sym2, cudaFuncAttributeMaxDynamicSharedMemorySize, SMEM_TOTAL);

    sq_kernel<<<(NB * NN) / 8, 256>>>(x);

    dim3 grid(NST * 2, 1, NB);   // 272 CTAs x 8 batches
    hyp_sym2<<<grid, THREADS, SMEM_TOTAL>>>(x, out);
}

// round 9
// speedup vs baseline: 1.8159x; 1.8159x over previous
#include <cuda_runtime.h>
#include <cuda_fp16.h>
#include <stdint.h>

#define NB 8
#define NN 4096
#define DD 512
#define TPD 32             // 128-tiles per dimension
#define NTILES 528         // upper triangle

#define BM 128
#define BN 128
#define BK 32              // fp16 k-chunk
#define NKT (DD / BK)      // 16
#define THREADS 256

#define STAGE_BYTES 20480  // A 10240 + B 10240 (128 rows x 80B, 64B data + 16B pad)
#define TS 132
#define SQROW_OFF  81920
#define INVROW_OFF 82432
#define SQCOL_OFF  82944
#define INVCOL_OFF 83456
#define SMEM_TOTAL 83968

__device__ float  g_sq[NB * NN];
__device__ __half g_xh[(size_t)NB * NN * DD];   // 32MB fp16 copy of inputs

static __device__ __forceinline__ uint32_t smem_u32(const void* p) {
    uint32_t a;
    asm("{ .reg .u64 t; cvta.to.shared.u64 t, %1; cvt.u32.u64 %0, t; }" : "=r"(a) : "l"(p));
    return a;
}

#define CP16(dst, src) \
    asm volatile("cp.async.cg.shared.global [%0], [%1], 16;" :: "r"(dst), "l"(src))
#define CP_COMMIT() asm volatile("cp.async.commit_group;" ::: "memory")
#define CP_WAIT(n)  asm volatile("cp.async.wait_group %0;" :: "n"(n) : "memory")

static __device__ __forceinline__ void ldsm4(uint32_t r[4], uint32_t addr) {
    asm volatile("ldmatrix.sync.aligned.m8n8.x4.shared.b16 {%0,%1,%2,%3}, [%4];"
                 : "=r"(r[0]), "=r"(r[1]), "=r"(r[2]), "=r"(r[3]) : "r"(addr));
}

static __device__ __forceinline__ void mma_f16(float c[4], const uint32_t a[4],
                                               const uint32_t b0, const uint32_t b1) {
    asm volatile(
        "mma.sync.aligned.m16n8k16.row.col.f32.f16.f16.f32 "
        "{%0,%1,%2,%3}, {%4,%5,%6,%7}, {%8,%9}, {%0,%1,%2,%3};\n"
        : "+f"(c[0]), "+f"(c[1]), "+f"(c[2]), "+f"(c[3])
        : "r"(a[0]), "r"(a[1]), "r"(a[2]), "r"(a[3]), "r"(b0), "r"(b1));
}

static __device__ __forceinline__ float fsqrt_ap(float x) {
    float y; asm("sqrt.approx.f32 %0, %1;" : "=f"(y) : "f"(x)); return y;
}

// ---------------------------------------------------------------------------
// Kernel 1: per-row squared norms (fp32-exact) + fp16 conversion of the row.
// One warp per row.
// ---------------------------------------------------------------------------
__global__ void prep_kernel(const float* __restrict__ x) {
    int row  = blockIdx.x * 8 + (threadIdx.x >> 5);
    int lane = threadIdx.x & 31;
    const float4* p = reinterpret_cast<const float4*>(x + (size_t)row * DD);
    __half* hrow = g_xh + (size_t)row * DD;
    float s = 0.0f;
#pragma unroll
    for (int i = 0; i < 4; ++i) {
        float4 v = p[lane + i * 32];
        s += v.x * v.x + v.y * v.y + v.z * v.z + v.w * v.w;
        __half2 h01 = __floats2half2_rn(v.x, v.y);
        __half2 h23 = __floats2half2_rn(v.z, v.w);
        uint2 pk;
        pk.x = *reinterpret_cast<uint32_t*>(&h01);
        pk.y = *reinterpret_cast<uint32_t*>(&h23);
        *reinterpret_cast<uint2*>(hrow + 4 * (lane + i * 32)) = pk;
    }
#pragma unroll
    for (int o = 16; o > 0; o >>= 1) s += __shfl_xor_sync(0xffffffffu, s, o);
    if (lane == 0) g_sq[row] = s;
}

// ---------------------------------------------------------------------------
// Kernel 2: symmetric upper-triangle fp16 Gram + fused hyperbolic epilogue.
// 128x128 tile, 8 warps (4x2, warp tile 32x64), cp.async 4-stage,
// smem-staged transpose for coalesced mirror writes. 2 CTAs/SM.
// ---------------------------------------------------------------------------
__global__ __launch_bounds__(THREADS, 2) void hyp_f16(float* __restrict__ out) {
    extern __shared__ __align__(1024) char smem[];
    const uint32_t sbase = smem_u32(smem);
    float* tileS   = reinterpret_cast<float*>(smem);
    float* sqRowS  = reinterpret_cast<float*>(smem + SQROW_OFF);
    float* invRowS = reinterpret_cast<float*>(smem + INVROW_OFF);
    float* sqColS  = reinterpret_cast<float*>(smem + SQCOL_OFF);
    float* invColS = reinterpret_cast<float*>(smem + INVCOL_OFF);

    const int b = blockIdx.z;
    int t = blockIdx.x, tr = 0;
    while (t >= TPD - tr) { t -= TPD - tr; ++tr; }
    const int tc = tr + t;
    const int rowBase = tr * BM;
    const int colBase = tc * BN;

    const int tid  = threadIdx.x;
    const int lane = tid & 31;
    const int wid  = tid >> 5;
    const int wr   = (wid & 3) * 32;
    const int wc   = (wid >> 2) * 64;
    const int gr   = lane >> 2;
    const int gq   = lane & 3;

    const __half* Xb = g_xh + (size_t)b * NN * DD;

    // cp.async geometry: 4 x 16B per thread per k-chunk (A 2, B 2)
    const int rowL = tid >> 2;          // 0..63
    const int seg  = tid & 3;           // 16B segment (BK=32 halves = 64B = 4 segs)
    const __half* pA0 = Xb + (size_t)(rowBase + rowL) * DD + seg * 8;
    const __half* pA1 = pA0 + (size_t)64 * DD;
    const __half* pB0 = Xb + (size_t)(colBase + rowL) * DD + seg * 8;
    const __half* pB1 = pB0 + (size_t)64 * DD;
    const uint32_t dOffA0 = (uint32_t)rowL * 80 + seg * 16;
    const uint32_t dOffA1 = dOffA0 + 64 * 80;

#define LOAD_TILE(g, s)                                                \
    do {                                                               \
        uint32_t sb = sbase + (uint32_t)(s) * STAGE_BYTES;             \
        CP16(sb + dOffA0,         pA0 + (size_t)(g) * BK);             \
        CP16(sb + dOffA1,         pA1 + (size_t)(g) * BK);             \
        CP16(sb + 10240 + dOffA0, pB0 + (size_t)(g) * BK);             \
        CP16(sb + 10240 + dOffA1, pB1 + (size_t)(g) * BK);             \
    } while (0)

    // ldmatrix per-lane offsets (same geometry as validated tf32 layout)
    uint32_t offA[2], offB[4];
#pragma unroll
    for (int mi = 0; mi < 2; ++mi) {
        int r = wr + mi * 16 + (lane & 15);
        offA[mi] = (uint32_t)r * 80 + (uint32_t)(lane >> 4) * 16;
    }
#pragma unroll
    for (int p = 0; p < 4; ++p) {
        int col = wc + (2 * p + (lane >> 4)) * 8 + (lane & 7);
        offB[p] = (uint32_t)col * 80 + ((lane >> 3) & 1) * 16;
    }

    if (tid < BM) {
        float s = g_sq[b * NN + rowBase + tid];
        sqRowS[tid] = s; invRowS[tid] = 1.0f / (1.0f - s);
    } else {
        int u = tid - BM;
        float s = g_sq[b * NN + colBase + u];
        sqColS[u] = s; invColS[u] = 1.0f / (1.0f - s);
    }

    LOAD_TILE(0, 0); CP_COMMIT();
    LOAD_TILE(1, 1); CP_COMMIT();
    LOAD_TILE(2, 2); CP_COMMIT();

    float c[2][8][4];
#pragma unroll
    for (int mi = 0; mi < 2; ++mi)
#pragma unroll
        for (int ni = 0; ni < 8; ++ni)
#pragma unroll
            for (int v = 0; v < 4; ++v) c[mi][ni][v] = 0.0f;

    for (int kt = 0; kt < NKT; ++kt) {
        CP_WAIT(2);
        __syncthreads();
        if (kt + 3 < NKT) LOAD_TILE(kt + 3, (kt + 3) & 3);
        CP_COMMIT();

        const uint32_t aSt = sbase + (uint32_t)(kt & 3) * STAGE_BYTES;
        const uint32_t bSt = aSt + 10240;
#pragma unroll
        for (int ks = 0; ks < 2; ++ks) {   // two k16 steps per BK=32
            uint32_t a[2][4], bb[4][4];
            ldsm4(a[0], aSt + offA[0] + ks * 32);
            ldsm4(a[1], aSt + offA[1] + ks * 32);
#pragma unroll
            for (int p = 0; p < 4; ++p) ldsm4(bb[p], bSt + offB[p] + ks * 32);
#pragma unroll
            for (int mi = 0; mi < 2; ++mi)
#pragma unroll
                for (int p = 0; p < 4; ++p) {
                    mma_f16(c[mi][2 * p + 0], a[mi], bb[p][0], bb[p][1]);
                    mma_f16(c[mi][2 * p + 1], a[mi], bb[p][2], bb[p][3]);
                }
        }
    }
    __syncthreads();   // mainloop done before tile staging reuses stage smem

    // ---- epilogue: hyperbolic distance -> smem tile ----
#pragma unroll
    for (int mi = 0; mi < 2; ++mi) {
#pragma unroll
        for (int half = 0; half < 2; ++half) {
            const int lr   = wr + mi * 16 + gr + half * 8;
            const int grow = rowBase + lr;
            const float si  = sqRowS[lr];
            const float tiv = 2.0f * invRowS[lr];
#pragma unroll
            for (int ni = 0; ni < 8; ++ni) {
                const int lcol = wc + ni * 8 + 2 * gq;
                const float g0 = c[mi][ni][half * 2 + 0];
                const float g1 = c[mi][ni][half * 2 + 1];
                float d20 = fmaxf(si + sqColS[lcol]     - 2.0f * g0, 0.0f);
                float d21 = fmaxf(si + sqColS[lcol + 1] - 2.0f * g1, 0.0f);
                float arg0 = fmaf(fsqrt_ap(d20), tiv * invColS[lcol],     1.0f);
                float arg1 = fmaf(fsqrt_ap(d21), tiv * invColS[lcol + 1], 1.0f);
                float t0 = fmaxf(fmaf(arg0, arg0, -1.0f), 0.0f);
                float t1 = fmaxf(fmaf(arg1, arg1, -1.0f), 0.0f);
                float dist0 = (arg0 > 1.0f) ? __logf(arg0 + fsqrt_ap(t0)) : 0.0f;
                float dist1 = (arg1 > 1.0f) ? __logf(arg1 + fsqrt_ap(t1)) : 0.0f;
                if (grow == colBase + lcol)     dist0 = 0.0f;
                if (grow == colBase + lcol + 1) dist1 = 0.0f;
                *reinterpret_cast<float2*>(tileS + lr * TS + lcol) = make_float2(dist0, dist1);
            }
        }
    }
    __syncthreads();

    // ---- direct write (coalesced float4 rows) ----
    {
        const int l4 = tid & 31;
        const int rw = tid >> 5;
#pragma unroll
        for (int i = 0; i < 16; ++i) {
            int r = rw + i * 8;
            float4 v = *reinterpret_cast<const float4*>(tileS + r * TS + l4 * 4);
            *reinterpret_cast<float4*>(out + ((size_t)b * NN + rowBase + r) * NN + colBase + l4 * 4) = v;
        }
    }
    // ---- mirror write (transpose read from smem, coalesced stores) ----
    if (tr != tc) {
        const int w = tid >> 5;
#pragma unroll
        for (int i = 0; i < 16; ++i) {
            int cc = w + i * 8;
            float* mrow = out + ((size_t)b * NN + colBase + cc) * NN + rowBase;
#pragma unroll
            for (int j = 0; j < 4; ++j)
                mrow[lane + 32 * j] = tileS[(lane + 32 * j) * TS + cc];
        }
    }
}

extern "C" void kernel_launch(void* const* d_in, const int* in_sizes, int n_in,
                              void* d_out, int out_size) {
    const float* x = (const float*)d_in[0];
    float* out = (float*)d_out;

    cudaFuncSetAttribute(hyp_f16, cudaFuncAttributeMaxDynamicSharedMemorySize, SMEM_TOTAL);

    prep_kernel<<<(NB * NN) / 8, 256>>>(x);

    dim3 grid(NTILES, 1, NB);   // 528 upper-triangle tiles x 8 batches
    hyp_f16<<<grid, THREADS, SMEM_TOTAL>>>(out);
}

// round 13
// speedup vs baseline: 2.2301x; 1.2281x over previous
#include <cuda_runtime.h>
#include <cuda_fp16.h>
#include <stdint.h>

#define NB 8
#define NN 4096
#define DD 512

// Supertile 256x256, CTA = 128x256 (row half h), warp tile 64x64 (8 warps 2x4)
#define SPD 16
#define NST 136               // SPD*(SPD+1)/2
#define BK 32                 // fp16 k-chunk
#define NKT (DD / BK)         // 16
#define THREADS 256

// stage: A 128 rows x 80B = 10240, B 256 rows x 80B = 20480
#define STAGE_BYTES 30720
#define SQROW_OFF  92160
#define INVROW_OFF 92672
#define SQCOL_OFF  93184
#define INVCOL_OFF 94208
#define SMEM_TOTAL 95232

__device__ float  g_sq[NB * NN];
__device__ __half g_xh[(size_t)NB * NN * DD];

static __device__ __forceinline__ uint32_t smem_u32(const void* p) {
    uint32_t a;
    asm("{ .reg .u64 t; cvta.to.shared.u64 t, %1; cvt.u32.u64 %0, t; }" : "=r"(a) : "l"(p));
    return a;
}

#define CP16(dst, src) \
    asm volatile("cp.async.cg.shared.global [%0], [%1], 16;" :: "r"(dst), "l"(src))
#define CP_COMMIT() asm volatile("cp.async.commit_group;" ::: "memory")
#define CP_WAIT(n)  asm volatile("cp.async.wait_group %0;" :: "n"(n) : "memory")

static __device__ __forceinline__ void ldsm4(uint32_t r[4], uint32_t addr) {
    asm volatile("ldmatrix.sync.aligned.m8n8.x4.shared.b16 {%0,%1,%2,%3}, [%4];"
                 : "=r"(r[0]), "=r"(r[1]), "=r"(r[2]), "=r"(r[3]) : "r"(addr));
}

// fp16-accumulate MMA: D,C packed half2 (2 regs)
static __device__ __forceinline__ void mma_f16h(uint32_t c[2], const uint32_t a[4],
                                                const uint32_t b0, const uint32_t b1) {
    asm volatile(
        "mma.sync.aligned.m16n8k16.row.col.f16.f16.f16.f16 "
        "{%0,%1}, {%2,%3,%4,%5}, {%6,%7}, {%0,%1};\n"
        : "+r"(c[0]), "+r"(c[1])
        : "r"(a[0]), "r"(a[1]), "r"(a[2]), "r"(a[3]), "r"(b0), "r"(b1));
}

static __device__ __forceinline__ float fsqrt_ap(float x) {
    float y; asm("sqrt.approx.f32 %0, %1;" : "=f"(y) : "f"(x)); return y;
}

// ---------------------------------------------------------------------------
// Kernel 1: per-row squared norms (fp32) + fp16 conversion
// ---------------------------------------------------------------------------
__global__ void prep_kernel(const float* __restrict__ x) {
    int row  = blockIdx.x * 8 + (threadIdx.x >> 5);
    int lane = threadIdx.x & 31;
    const float4* p = reinterpret_cast<const float4*>(x + (size_t)row * DD);
    __half* hrow = g_xh + (size_t)row * DD;
    float s = 0.0f;
#pragma unroll
    for (int i = 0; i < 4; ++i) {
        float4 v = p[lane + i * 32];
        s += v.x * v.x + v.y * v.y + v.z * v.z + v.w * v.w;
        __half2 h01 = __floats2half2_rn(v.x, v.y);
        __half2 h23 = __floats2half2_rn(v.z, v.w);
        uint2 pk;
        pk.x = *reinterpret_cast<uint32_t*>(&h01);
        pk.y = *reinterpret_cast<uint32_t*>(&h23);
        *reinterpret_cast<uint2*>(hrow + 4 * (lane + i * 32)) = pk;
    }
#pragma unroll
    for (int o = 16; o > 0; o >>= 1) s += __shfl_xor_sync(0xffffffffu, s, o);
    if (lane == 0) g_sq[row] = s;
}

// ---------------------------------------------------------------------------
// Kernel 2: symmetric supertile fp16 Gram (fp16 acc) + fused hyperbolic
// epilogue. CTA 128x256, 8 warps 2x4, warp tile 64x64, cp.async 3-stage,
// direct + mirror writes straight from registers. 2 CTAs/SM.
// ---------------------------------------------------------------------------
__global__ __launch_bounds__(THREADS, 2) void hyp_f16a(float* __restrict__ out) {
    extern __shared__ __align__(1024) char smem[];
    const uint32_t sbase = smem_u32(smem);
    float* sqRowS  = reinterpret_cast<float*>(smem + SQROW_OFF);
    float* invRowS = reinterpret_cast<float*>(smem + INVROW_OFF);
    float* sqColS  = reinterpret_cast<float*>(smem + SQCOL_OFF);
    float* invColS = reinterpret_cast<float*>(smem + INVCOL_OFF);

    const int b = blockIdx.z;
    int st = blockIdx.x >> 1;
    const int h = blockIdx.x & 1;
    int TR = 0;
    while (st >= SPD - TR) { st -= SPD - TR; ++TR; }
    const int TC = TR + st;
    const int rowBase = TR * 256 + h * 128;
    const int colBase = TC * 256;

    const int tid  = threadIdx.x;
    const int lane = tid & 31;
    const int wid  = tid >> 5;
    const int wr   = (wid & 1) * 64;
    const int wc   = (wid >> 1) * 64;
    const int gr   = lane >> 2;
    const int gq   = lane & 3;

    const __half* Xb = g_xh + (size_t)b * NN * DD;

    // cp.async: 6 x 16B per thread per k-chunk
    const int rowT = tid >> 2;           // 0..63
    const int seg  = tid & 3;            // 16B segment of 64B k-row
    const __half* pA0 = Xb + (size_t)(rowBase + rowT) * DD + seg * 8;
    const __half* pB0 = Xb + (size_t)(colBase + rowT) * DD + seg * 8;
    const uint32_t dA0 = (uint32_t)rowT * 80 + seg * 16;

#define LOAD_TILE(g, s)                                                        \
    do {                                                                       \
        uint32_t sb = sbase + (uint32_t)(s) * STAGE_BYTES;                     \
        const __half* ga = pA0 + (size_t)(g) * BK;                             \
        const __half* gb = pB0 + (size_t)(g) * BK;                             \
        CP16(sb + dA0,           ga);                                          \
        CP16(sb + dA0 + 64 * 80, ga + (size_t)64 * DD);                        \
        CP16(sb + 10240 + dA0,            gb);                                 \
        CP16(sb + 10240 + dA0 +  64 * 80, gb + (size_t)64  * DD);              \
        CP16(sb + 10240 + dA0 + 128 * 80, gb + (size_t)128 * DD);              \
        CP16(sb + 10240 + dA0 + 192 * 80, gb + (size_t)192 * DD);              \
    } while (0)

    // ldmatrix per-lane offsets (validated fp16 geometry)
    uint32_t offA[4], offB[4];
#pragma unroll
    for (int mi = 0; mi < 4; ++mi) {
        int r = wr + mi * 16 + (lane & 15);
        offA[mi] = (uint32_t)r * 80 + (uint32_t)(lane >> 4) * 16;
    }
#pragma unroll
    for (int p = 0; p < 4; ++p) {
        int col = wc + (2 * p + (lane >> 4)) * 8 + (lane & 7);
        offB[p] = (uint32_t)col * 80 + ((lane >> 3) & 1) * 16;
    }

    // stage sq / 1/(1-sq)
    {
        float sc = g_sq[b * NN + colBase + tid];
        sqColS[tid] = sc; invColS[tid] = 1.0f / (1.0f - sc);
        if (tid < 128) {
            float sr = g_sq[b * NN + rowBase + tid];
            sqRowS[tid] = sr; invRowS[tid] = 1.0f / (1.0f - sr);
        }
    }

    LOAD_TILE(0, 0); CP_COMMIT();
    LOAD_TILE(1, 1); CP_COMMIT();

    uint32_t c[4][8][2];
#pragma unroll
    for (int mi = 0; mi < 4; ++mi)
#pragma unroll
        for (int ni = 0; ni < 8; ++ni) { c[mi][ni][0] = 0u; c[mi][ni][1] = 0u; }

    int stg = 0;                       // stage of k-tile kt
    for (int kt = 0; kt < NKT; ++kt) {
        CP_WAIT(1);                    // k-tile kt resident
        __syncthreads();               // compute(kt-1) done -> its stage free
        if (kt + 2 < NKT) {
            int s2 = stg + 2; if (s2 >= 3) s2 -= 3;
            LOAD_TILE(kt + 2, s2);
        }
        CP_COMMIT();

        const uint32_t aSt = sbase + (uint32_t)stg * STAGE_BYTES;
        const uint32_t bSt = aSt + 10240;
#pragma unroll
        for (int ks = 0; ks < 2; ++ks) {
            uint32_t a[4][4], bb[4][4];
#pragma unroll
            for (int mi = 0; mi < 4; ++mi) ldsm4(a[mi], aSt + offA[mi] + ks * 32);
#pragma unroll
            for (int p = 0; p < 4; ++p)    ldsm4(bb[p], bSt + offB[p] + ks * 32);
#pragma unroll
            for (int mi = 0; mi < 4; ++mi)
#pragma unroll
                for (int p = 0; p < 4; ++p) {
                    mma_f16h(c[mi][2 * p + 0], a[mi], bb[p][0], bb[p][1]);
                    mma_f16h(c[mi][2 * p + 1], a[mi], bb[p][2], bb[p][3]);
                }
        }
        if (++stg == 3) stg = 0;
    }

    // ---- epilogue: hyperbolic distance, direct + mirror from registers ----
    const bool doMirror = (TR != TC);
#pragma unroll
    for (int mi = 0; mi < 4; ++mi) {
#pragma unroll
        for (int hh = 0; hh < 2; ++hh) {
            const int lr   = wr + mi * 16 + hh * 8 + gr;
            const int grow = rowBase + lr;
            const float si  = sqRowS[lr];
            const float tiv = 2.0f * invRowS[lr];
            float* orow = out + ((size_t)b * NN + grow) * NN + colBase;
#pragma unroll
            for (int ni = 0; ni < 8; ++ni) {
                const int lcol = wc + ni * 8 + 2 * gq;
                const __half2 hv = *reinterpret_cast<const __half2*>(&c[mi][ni][hh]);
                const float2 gf = __half22float2(hv);
                float d20 = fmaxf(si + sqColS[lcol]     - 2.0f * gf.x, 0.0f);
                float d21 = fmaxf(si + sqColS[lcol + 1] - 2.0f * gf.y, 0.0f);
                float arg0 = fmaf(fsqrt_ap(d20), tiv * invColS[lcol],     1.0f);
                float arg1 = fmaf(fsqrt_ap(d21), tiv * invColS[lcol + 1], 1.0f);
                float t0 = fmaxf(fmaf(arg0, arg0, -1.0f), 0.0f);
                float t1 = fmaxf(fmaf(arg1, arg1, -1.0f), 0.0f);
                float dist0 = (arg0 > 1.0f) ? __logf(arg0 + fsqrt_ap(t0)) : 0.0f;
                float dist1 = (arg1 > 1.0f) ? __logf(arg1 + fsqrt_ap(t1)) : 0.0f;
                if (grow == colBase + lcol)     dist0 = 0.0f;
                if (grow == colBase + lcol + 1) dist1 = 0.0f;
                *reinterpret_cast<float2*>(orow + lcol) = make_float2(dist0, dist1);
                if (doMirror) {
                    out[((size_t)b * NN + colBase + lcol)     * NN + grow] = dist0;
                    out[((size_t)b * NN + colBase + lcol + 1) * NN + grow] = dist1;
                }
            }
        }
    }
}

extern "C" void kernel_launch(void* const* d_in, const int* in_sizes, int n_in,
                              void* d_out, int out_size) {
    const float* x = (const float*)d_in[0];
    float* out = (float*)d_out;

    cudaFuncSetAttribute(hyp_f16a, cudaFuncAttributeMaxDynamicSharedMemorySize, SMEM_TOTAL);

    prep_kernel<<<(NB * NN) / 8, 256>>>(x);

    dim3 grid(NST * 2, 1, NB);   // 272 x 8
    hyp_f16a<<<grid, THREADS, SMEM_TOTAL>>>(out);
}